// round 2
// baseline (speedup 1.0000x reference)
#include <cuda_runtime.h>
#include <math.h>

#define NN 100000
#define EE 600000
#define GG 512
#define IND 74
#define HH 128
#define TM 8
#define SCAN_B 512
#define NSB ((NN + SCAN_B - 1) / SCAN_B)   // 196

// ---- scratch (device globals; no allocation allowed) ----
__device__ float d_h0[NN * IND];
__device__ float d_h1[NN * HH];
__device__ float d_h2[NN * HH];
__device__ float d_agg[NN * HH];
__device__ float d_invdeg[NN];
__device__ int   d_degi[NN];
__device__ int   d_cursor[NN];
__device__ int   d_rowstart[NN + 1];
__device__ int   d_eid[EE];
__device__ int   d_bsum[NSB];
__device__ int   d_boff[NSB];
__device__ float d_psum[GG * HH];
__device__ float d_pmax[GG * HH];
__device__ float d_cnt[GG];

// ---------------------------------------------------------------------------
__global__ void k_init0() {
    int i = blockIdx.x * blockDim.x + threadIdx.x;
    if (i < NN) { d_degi[i] = 0; d_cursor[i] = 0; }
    if (i < GG * HH) { d_psum[i] = 0.f; d_pmax[i] = __int_as_float(0xFF800000); }
    if (i < GG) d_cnt[i] = 0.f;
}

__global__ void k_build_h0(const float* __restrict__ x,
                           const float* __restrict__ xd,
                           const int* __restrict__ st,
                           const float* __restrict__ emb) {
    int idx = blockIdx.x * blockDim.x + threadIdx.x;
    if (idx >= NN * IND) return;
    int n = idx / IND;
    int j = idx - n * IND;
    float v;
    if (j < 60)      v = x[n * 60 + j];
    else if (j < 62) v = xd[n * 2 + (j - 60)];
    else             v = emb[st[n] * 12 + (j - 62)];
    d_h0[idx] = v;
}

__global__ void k_deg(const int* __restrict__ dst) {
    int e = blockIdx.x * blockDim.x + threadIdx.x;
    if (e < EE) atomicAdd(&d_degi[dst[e]], 1);
}

// block-local inclusive scan -> exclusive per-element + block totals
__global__ void __launch_bounds__(SCAN_B)
k_scan1() {
    __shared__ int sc[SCAN_B];
    int tid = threadIdx.x;
    int i = blockIdx.x * SCAN_B + tid;
    int v = (i < NN) ? d_degi[i] : 0;
    sc[tid] = v;
    __syncthreads();
#pragma unroll
    for (int off = 1; off < SCAN_B; off <<= 1) {
        int t = (tid >= off) ? sc[tid - off] : 0;
        __syncthreads();
        sc[tid] += t;
        __syncthreads();
    }
    if (i < NN) {
        d_rowstart[i] = sc[tid] - v;          // local exclusive
        d_invdeg[i] = 1.f / fmaxf((float)v, 1.f);
    }
    if (tid == SCAN_B - 1) d_bsum[blockIdx.x] = sc[tid];
}

__global__ void k_scan2() {
    if (threadIdx.x == 0 && blockIdx.x == 0) {
        int run = 0;
        for (int b = 0; b < NSB; b++) { d_boff[b] = run; run += d_bsum[b]; }
        d_rowstart[NN] = EE;
    }
}

__global__ void k_scan3() {
    int i = blockIdx.x * blockDim.x + threadIdx.x;
    if (i < NN) d_rowstart[i] += d_boff[i / SCAN_B];
}

__global__ void k_fill(const int* __restrict__ src, const int* __restrict__ dst) {
    int e = blockIdx.x * blockDim.x + threadIdx.x;
    if (e >= EE) return;
    int dn = dst[e];
    int pos = d_rowstart[dn] + atomicAdd(&d_cursor[dn], 1);
    d_eid[pos] = src[e];
}

// gather aggregation: one block per node, threads over channels.
// writes agg * invdeg (pre-scaled).
template <int D>
__global__ void __launch_bounds__(128)
k_gather(const float* __restrict__ h) {
    int n = blockIdx.x;
    int d = threadIdx.x;
    if (d >= D) return;
    int s = d_rowstart[n];
    int t = d_rowstart[n + 1];
    float acc = 0.f;
    for (int j = s; j < t; j++)
        acc += h[(size_t)d_eid[j] * D + d];
    d_agg[n * D + d] = acc * d_invdeg[n];
}

// Fused: agg@Wl + bl + h@Wr -> LayerNorm -> ReLU
// blockDim = 128 (one thread per output channel), TM nodes per block.
template <int K>
__global__ void __launch_bounds__(128)
k_sage(const float* __restrict__ Wl, const float* __restrict__ bl,
       const float* __restrict__ Wr, const float* __restrict__ g,
       const float* __restrict__ bn, const float* __restrict__ hin,
       float* __restrict__ hout) {
    __shared__ float sA[TM][K];
    __shared__ float sH[TM][K];
    __shared__ float red[4];

    const int o = threadIdx.x;
    const int n0 = blockIdx.x * TM;

    for (int idx = o; idx < TM * K; idx += 128) {
        int m = idx / K;
        int k = idx - m * K;
        int n = n0 + m;
        if (n < NN) {
            sA[m][k] = d_agg[n * K + k];
            sH[m][k] = hin[(size_t)n * K + k];
        } else {
            sA[m][k] = 0.f;
            sH[m][k] = 0.f;
        }
    }
    __syncthreads();

    float acc[TM];
    const float bias = bl[o];
#pragma unroll
    for (int m = 0; m < TM; m++) acc[m] = bias;

#pragma unroll 2
    for (int k = 0; k < K; k++) {
        float wl = Wl[k * HH + o];
        float wr = Wr[k * HH + o];
#pragma unroll
        for (int m = 0; m < TM; m++)
            acc[m] += sA[m][k] * wl + sH[m][k] * wr;
    }

    const float gam = g[o];
    const float bet = bn[o];
    const int lane = o & 31;
    const int w = o >> 5;

    for (int m = 0; m < TM; m++) {
        int n = n0 + m;
        if (n >= NN) break;   // uniform across block (NN % TM == 0 anyway)
        float v = acc[m];

        float s = v;
#pragma unroll
        for (int off = 16; off; off >>= 1) s += __shfl_xor_sync(~0u, s, off);
        if (lane == 0) red[w] = s;
        __syncthreads();
        float mu = (red[0] + red[1] + red[2] + red[3]) * (1.f / HH);
        __syncthreads();

        float dv = v - mu;
        float s2 = dv * dv;
#pragma unroll
        for (int off = 16; off; off >>= 1) s2 += __shfl_xor_sync(~0u, s2, off);
        if (lane == 0) red[w] = s2;
        __syncthreads();
        float var = (red[0] + red[1] + red[2] + red[3]) * (1.f / HH);
        __syncthreads();

        float y = dv * rsqrtf(var + 1e-5f) * gam + bet;
        hout[(size_t)n * HH + o] = fmaxf(y, 0.f);
    }
}

__global__ void k_cnt(const int* __restrict__ batch) {
    int n = blockIdx.x * blockDim.x + threadIdx.x;
    if (n < NN) atomicAdd(&d_cnt[batch[n]], 1.f);
}

__global__ void k_pool(const int* __restrict__ batch) {
    int i = blockIdx.x * blockDim.x + threadIdx.x;
    if (i >= NN * HH) return;
    int n = i >> 7;
    int d = i & 127;
    int gidx = batch[n];
    float v = d_h2[i];
    atomicAdd(&d_psum[gidx * HH + d], v);
    // v >= 0 (post-ReLU) so int-bit compare is order-preserving
    atomicMax((int*)&d_pmax[gidx * HH + d], __float_as_int(v));
}

__global__ void __launch_bounds__(64)
k_mlp(const float* __restrict__ Wf0, const float* __restrict__ bf0,
      const float* __restrict__ Wf1, const float* __restrict__ bf1,
      const float* __restrict__ Wf2, const float* __restrict__ bf2,
      float* __restrict__ out) {
    __shared__ float z[2 * HH];
    __shared__ float t1[50];
    __shared__ float t2[50];
    int gg = blockIdx.x;
    int t = threadIdx.x;

    float c = fmaxf(d_cnt[gg], 1.f);
    for (int d = t; d < 2 * HH; d += 64)
        z[d] = (d < HH) ? d_psum[gg * HH + d] / c : d_pmax[gg * HH + (d - HH)];
    __syncthreads();

    if (t < 50) {
        float s = bf0[t];
        for (int k = 0; k < 2 * HH; k++) s += z[k] * Wf0[k * 50 + t];
        t1[t] = fmaxf(s, 0.f);
    }
    __syncthreads();
    if (t < 50) {
        float s = bf1[t];
        for (int k = 0; k < 50; k++) s += t1[k] * Wf1[k * 50 + t];
        t2[t] = fmaxf(s, 0.f);
    }
    __syncthreads();
    if (t < 10) {
        float s = bf2[t];
        for (int k = 0; k < 50; k++) s += t2[k] * Wf2[k * 10 + t];   // (50,10): stride 10
        out[gg * 10 + t] = fmaxf(s, 0.f);
    }
}

// ---------------------------------------------------------------------------
static inline int cdiv(long long a, int b) { return (int)((a + b - 1) / b); }

extern "C" void kernel_launch(void* const* d_in, const int* in_sizes, int n_in,
                              void* d_out, int out_size) {
    const float* x      = (const float*)d_in[0];
    const float* xdims  = (const float*)d_in[1];
    const int*   st     = (const int*)d_in[2];
    const int*   ei     = (const int*)d_in[3];
    const int*   batch  = (const int*)d_in[4];
    const float* emb    = (const float*)d_in[5];
    const float* Wl0 = (const float*)d_in[6];
    const float* bl0 = (const float*)d_in[7];
    const float* Wr0 = (const float*)d_in[8];
    const float* g0  = (const float*)d_in[9];
    const float* bn0 = (const float*)d_in[10];
    const float* Wl1 = (const float*)d_in[11];
    const float* bl1 = (const float*)d_in[12];
    const float* Wr1 = (const float*)d_in[13];
    const float* g1  = (const float*)d_in[14];
    const float* bn1 = (const float*)d_in[15];
    const float* Wf0 = (const float*)d_in[16];
    const float* bf0 = (const float*)d_in[17];
    const float* Wf1 = (const float*)d_in[18];
    const float* bf1 = (const float*)d_in[19];
    const float* Wf2 = (const float*)d_in[20];
    const float* bf2 = (const float*)d_in[21];
    float* out = (float*)d_out;

    const int* src = ei;
    const int* dst = ei + EE;

    float* p_h0 = nullptr;
    float* p_h1 = nullptr;
    float* p_h2 = nullptr;
    cudaGetSymbolAddress((void**)&p_h0, d_h0);
    cudaGetSymbolAddress((void**)&p_h1, d_h1);
    cudaGetSymbolAddress((void**)&p_h2, d_h2);

    // init + node features + CSR build (shared by both layers)
    k_init0<<<cdiv(NN, 256), 256>>>();
    k_build_h0<<<cdiv((long long)NN * IND, 256), 256>>>(x, xdims, st, emb);
    k_deg<<<cdiv(EE, 256), 256>>>(dst);
    k_scan1<<<NSB, SCAN_B>>>();
    k_scan2<<<1, 32>>>();
    k_scan3<<<cdiv(NN, 256), 256>>>();
    k_fill<<<cdiv(EE, 256), 256>>>(src, dst);

    // ---- layer 0 ----
    k_gather<IND><<<NN, 128>>>(p_h0);
    k_sage<IND><<<cdiv(NN, TM), 128>>>(Wl0, bl0, Wr0, g0, bn0, p_h0, p_h1);

    // ---- layer 1 ----
    k_gather<HH><<<NN, 128>>>(p_h1);
    k_sage<HH><<<cdiv(NN, TM), 128>>>(Wl1, bl1, Wr1, g1, bn1, p_h1, p_h2);

    // ---- pooling ----
    k_cnt<<<cdiv(NN, 256), 256>>>(batch);
    k_pool<<<cdiv((long long)NN * HH, 256), 256>>>(batch);

    // ---- MLP head ----
    k_mlp<<<GG, 64>>>(Wf0, bf0, Wf1, bf1, Wf2, bf2, out);
}